// round 2
// baseline (speedup 1.0000x reference)
#include <cuda_runtime.h>
#include <math.h>

#define NN 1024
#define NT 256
#define BB 32

// ---------------- device scratch (no allocations allowed) ----------------
__device__ float2   g_pa[BB * NN];        // analytic signal per batch
__device__ float2   g_pam[BB * NN];       // analytic signal * exp(-i*phi*(t-512))
__device__ float2   g_tw[NN / 2];         // forward twiddles e^{-2pi i k / N}
__device__ double   g_accS[BB], g_accST[BB], g_accT[BB], g_accT2[BB];
__device__ unsigned g_accMax[BB];

__device__ __forceinline__ float2 cmulf(float2 a, float2 b) {
    return make_float2(a.x * b.x - a.y * b.y, a.x * b.y + a.y * b.x);
}

// In-place 1024-pt complex FFT in shared memory, 256 threads.
// DIT radix-2 with bit-reversal. INV=true -> inverse (conj twiddles + 1/N).
template <bool INV>
__device__ __forceinline__ void fft1024(float2* sm, const float2* tw, int tid) {
#pragma unroll
    for (int e = 0; e < 4; e++) {
        int i = tid + e * NT;
        int j = __brev(i) >> 22;
        if (i < j) { float2 t = sm[i]; sm[i] = sm[j]; sm[j] = t; }
    }
    __syncthreads();
#pragma unroll
    for (int s = 1; s <= 10; s++) {
        int half = 1 << (s - 1);
#pragma unroll
        for (int e = 0; e < 2; e++) {
            int m   = tid + e * NT;
            int pos = m & (half - 1);
            int i0  = ((m >> (s - 1)) << s) + pos;
            int i1  = i0 + half;
            float2 w = tw[pos << (10 - s)];
            float wy = INV ? -w.y : w.y;
            float2 q = sm[i1];
            float2 v = make_float2(q.x * w.x - q.y * wy, q.x * wy + q.y * w.x);
            float2 u = sm[i0];
            sm[i0] = make_float2(u.x + v.x, u.y + v.y);
            sm[i1] = make_float2(u.x - v.x, u.y - v.y);
        }
        __syncthreads();
    }
    if (INV) {
        const float sc = 1.0f / (float)NN;
#pragma unroll
        for (int e = 0; e < 4; e++) { int i = tid + e * NT; sm[i].x *= sc; sm[i].y *= sc; }
        __syncthreads();
    }
}

// ---------------- kernel 1: init accumulators + twiddles + output ----------------
__global__ void init_kernel(float* out) {
    int t = threadIdx.x;
    if (t == 0) out[0] = 0.0f;
    if (t < BB) {
        g_accS[t] = 0.0; g_accST[t] = 0.0; g_accT[t] = 0.0; g_accT2[t] = 0.0;
        g_accMax[t] = 0u;
    }
    if (t < NN / 2) {
        double ang = -2.0 * 3.14159265358979323846 * (double)t / (double)NN;
        g_tw[t] = make_float2((float)cos(ang), (float)sin(ang));
    }
}

// ---------------- kernel 2: hilbert (analytic signal) + modulation ----------------
__global__ void hilbert_kernel(const float* __restrict__ pred) {
    __shared__ float2 sm[NN];
    __shared__ float2 tw[NN / 2];
    int b = blockIdx.x, tid = threadIdx.x;
#pragma unroll
    for (int e = 0; e < 2; e++) tw[tid + e * NT] = g_tw[tid + e * NT];
#pragma unroll
    for (int e = 0; e < 4; e++) {
        int i = tid + e * NT;
        sm[i] = make_float2(pred[b * NN + i], 0.0f);
    }
    __syncthreads();
    fft1024<false>(sm, tw, tid);
#pragma unroll
    for (int e = 0; e < 4; e++) {
        int i = tid + e * NT;
        float h = (i < NN / 2) ? 0.0f : ((i == NN / 2) ? 1.0f : 2.0f);
        sm[i].x *= h; sm[i].y *= h;
    }
    __syncthreads();
    fft1024<true>(sm, tw, tid);
#pragma unroll
    for (int e = 0; e < 4; e++) {
        int i = tid + e * NT;
        float2 a = sm[i];
        g_pa[b * NN + i] = a;
        // SHIFT_FACTOR along the time axis: exp(-i * 2*W_CENTER*DELTA_TAU * (t-512)),
        // angle computed in double then rounded to float32 like the reference.
        float ang = (float)(2.0 * 1175000000000000.0 * 1.5e-15 * (double)(i - 512));
        float cs, sn;
        __sincosf(ang, &sn, &cs);
        // use accurate sin/cos (not fast intrinsic) to match numpy closely:
        cs = cosf(ang); sn = sinf(ang);
        g_pam[b * NN + i] = cmulf(a, make_float2(cs, -sn));
    }
}

// ---------------- kernel 3: SHG trace, fused reductions ----------------
// Row d: c[t] = pam[t] * pa[(t-(d-512)) & 1023]; S[d,k] = DT^2 |FFT(c)|^2 at column k^512
// (outer fftshift). Inner fftshift only changes FFT phases -> magnitude invariant.
#define RPB 4
__global__ void shg_kernel(const float* __restrict__ tref) {
    __shared__ float2 paS[NN];
    __shared__ float2 pamS[NN];
    __shared__ float2 work[NN];
    __shared__ float2 tw[NN / 2];
    int b = blockIdx.y, tid = threadIdx.x;
#pragma unroll
    for (int e = 0; e < 2; e++) tw[tid + e * NT] = g_tw[tid + e * NT];
#pragma unroll
    for (int e = 0; e < 4; e++) {
        int i = tid + e * NT;
        paS[i]  = g_pa[b * NN + i];
        pamS[i] = g_pam[b * NN + i];
    }
    __syncthreads();

    const float DT2 = 2.25e-30f;  // DELTA_TAU^2
    const float* base = tref + (size_t)b * NN * NN;

    float  lmax = 0.0f;
    double dS = 0.0, dST = 0.0, dT = 0.0, dT2 = 0.0;

#pragma unroll
    for (int rr = 0; rr < RPB; rr++) {
        int d = blockIdx.x * RPB + rr;   // 0..1023
        int delay = d - 512;
#pragma unroll
        for (int e = 0; e < 4; e++) {
            int t  = tid + e * NT;
            int t2 = (t - delay) & (NN - 1);
            work[t] = cmulf(pamS[t], paS[t2]);
        }
        __syncthreads();
        fft1024<false>(work, tw, tid);

        const float* row = base + (size_t)d * NN;
        float rS = 0.0f, rST = 0.0f, rT = 0.0f, rT2 = 0.0f;
#pragma unroll
        for (int e = 0; e < 4; e++) {
            int k = tid + e * NT;
            float2 X = work[k];
            float Sv = (X.x * X.x + X.y * X.y) * DT2;
            int col = k ^ 512;  // outer fftshift column mapping
            float tv = row[col];
            lmax = fmaxf(lmax, Sv);
            rS  += Sv;
            rST += Sv * tv;
            rT  += tv;
            rT2 += tv * tv;
        }
        dS += rS; dST += rST; dT += rT; dT2 += rT2;
        __syncthreads();
    }

    // block reduction
    double vS = dS, vST = dST, vT = dT, vT2 = dT2; float vM = lmax;
#pragma unroll
    for (int o = 16; o > 0; o >>= 1) {
        vS  += __shfl_down_sync(0xffffffffu, vS,  o);
        vST += __shfl_down_sync(0xffffffffu, vST, o);
        vT  += __shfl_down_sync(0xffffffffu, vT,  o);
        vT2 += __shfl_down_sync(0xffffffffu, vT2, o);
        vM   = fmaxf(vM, __shfl_down_sync(0xffffffffu, vM, o));
    }
    __shared__ double sS[8], sST[8], sT[8], sT2[8];
    __shared__ float  sM[8];
    int w = tid >> 5, lane = tid & 31;
    if (lane == 0) { sS[w] = vS; sST[w] = vST; sT[w] = vT; sT2[w] = vT2; sM[w] = vM; }
    __syncthreads();
    if (tid == 0) {
        double aS = 0, aST = 0, aT = 0, aT2 = 0; float aM = 0.0f;
#pragma unroll
        for (int i = 0; i < 8; i++) {
            aS += sS[i]; aST += sST[i]; aT += sT[i]; aT2 += sT2[i];
            aM = fmaxf(aM, sM[i]);
        }
        atomicAdd(&g_accS[b],  aS);
        atomicAdd(&g_accST[b], aST);
        atomicAdd(&g_accT[b],  aT);
        atomicAdd(&g_accT2[b], aT2);
        atomicMax(&g_accMax[b], __float_as_uint(aM));  // S >= 0: bit order == value order
    }
}

// ---------------- kernel 4: MSE terms + frog + final mean ----------------
__global__ void loss_kernel(const float* __restrict__ label, float* out) {
    int b = blockIdx.x, tid = threadIdx.x;
    const float* lr = label + (size_t)b * 2 * NN;
    const float* li = lr + NN;

    __shared__ int s_frR, s_laR, s_frI, s_laI;
    if (tid == 0) { s_frR = NN; s_laR = -1; s_frI = NN; s_laI = -1; }
    __syncthreads();
    int frR = NN, laR = -1, frI = NN, laI = -1;
    for (int t = tid; t < NN; t += NT) {
        if (fabsf(lr[t]) > 0.01f) { frR = min(frR, t); laR = max(laR, t); }
        if (fabsf(li[t]) > 0.01f) { frI = min(frI, t); laI = max(laI, t); }
    }
    atomicMin(&s_frR, frR); atomicMax(&s_laR, laR);
    atomicMin(&s_frI, frI); atomicMax(&s_laI, laI);
    __syncthreads();
    int fr_r = (s_frR == NN) ? 0 : s_frR;
    int la_r = (s_laR < 0) ? (NN - 1) : s_laR;
    int fr_i = (s_frI == NN) ? 0 : s_frI;
    int la_i = (s_laI < 0) ? (NN - 1) : s_laI;
    int first = min(fr_r, fr_i);
    int last  = max(la_r, la_i);

    float sR = 0, sI = 0, sInt = 0, sPh = 0;
    for (int t = tid; t < NN; t += NT) {
        float2 p = g_pa[b * NN + t];
        float LR = lr[t], LI = li[t];
        bool inr = (t >= first) && (t < last);
        float pm = inr ? 10.0f : 1.0f;  // PENALTY
        float dr = p.x - LR, di = p.y - LI;
        float pint = p.x * p.x + p.y * p.y;
        float lint = LR * LR + LI * LI;
        float dint = pint - lint;
        sR   += dr * dr * pm;
        sI   += di * di * pm;
        sInt += dint * dint * pm;
        if (inr) {
            float dp = atan2f(p.y, p.x) - atan2f(LI, LR);
            sPh += dp * dp;
        }
    }
#pragma unroll
    for (int o = 16; o > 0; o >>= 1) {
        sR   += __shfl_down_sync(0xffffffffu, sR, o);
        sI   += __shfl_down_sync(0xffffffffu, sI, o);
        sInt += __shfl_down_sync(0xffffffffu, sInt, o);
        sPh  += __shfl_down_sync(0xffffffffu, sPh, o);
    }
    __shared__ float rA[8], rBv[8], rC[8], rD[8];
    int w = tid >> 5, lane = tid & 31;
    if (lane == 0) { rA[w] = sR; rBv[w] = sI; rC[w] = sInt; rD[w] = sPh; }
    __syncthreads();
    if (tid == 0) {
        float aR = 0, aI = 0, aInt = 0, aPh = 0;
#pragma unroll
        for (int i = 0; i < 8; i++) { aR += rA[i]; aI += rBv[i]; aInt += rC[i]; aPh += rD[i]; }
        float mse = (aR + aI + aInt + aPh) * (1.0f / NN) * 0.25f;  // /MSE_WSUM

        double M    = (double)__uint_as_float(g_accMax[b]);
        double sum1 = g_accST[b] / M;
        double mu   = sum1 / g_accT2[b];
        double diff = g_accS[b] / M - mu * g_accT[b];
        double r2   = diff * diff;
        // after normalization max(shg_pred)=1 exactly -> norm = N*N
        float frog = (r2 == 0.0) ? 0.0f : (float)(sqrt(r2) / (double)NN);

        atomicAdd(out, (mse + frog) * (1.0f / BB));
    }
}

// ---------------- launch ----------------
extern "C" void kernel_launch(void* const* d_in, const int* in_sizes, int n_in,
                              void* d_out, int out_size) {
    const float* pred  = (const float*)d_in[0];  // (B, N)
    const float* label = (const float*)d_in[1];  // (B, 2N)
    const float* shg   = (const float*)d_in[2];  // (B, 1, N, N)
    float* out = (float*)d_out;

    init_kernel<<<1, 512>>>(out);
    hilbert_kernel<<<BB, NT>>>(pred);
    shg_kernel<<<dim3(NN / RPB, BB), NT>>>(shg);
    loss_kernel<<<BB, NT>>>(label, out);
}

// round 3
// speedup vs baseline: 3.7850x; 3.7850x over previous
#include <cuda_runtime.h>
#include <math.h>

#define NN 1024
#define NT 256
#define BB 32

// ---------------- device scratch ----------------
__device__ float2   g_pa[BB * NN];
__device__ float2   g_pam[BB * NN];
__device__ float2   g_tw[512];            // W_1024^k, k<512
__device__ double   g_accS[BB], g_accST[BB], g_accT[BB], g_accT2[BB];
__device__ unsigned g_accMax[BB];

__device__ __forceinline__ float2 cmulf(float2 a, float2 b) {
    return make_float2(a.x * b.x - a.y * b.y, a.x * b.y + a.y * b.x);
}
__device__ __forceinline__ float2 cadd(float2 a, float2 b) { return make_float2(a.x + b.x, a.y + b.y); }
__device__ __forceinline__ float2 csub(float2 a, float2 b) { return make_float2(a.x - b.x, a.y - b.y); }

// group barrier: 64 threads (2 warps), named barrier per group
__device__ __forceinline__ void gbar(int id) {
    asm volatile("bar.sync %0, %1;" :: "r"(id), "r"(64) : "memory");
}

// forward DIF radix-4 butterfly; inputs at q, q+L/4, q+L/2, q+3L/4 (a,b,c,d)
#define BFLY4(A, Bq, C, D, W1, W2, W3) do {                                   \
    float2 t0 = cadd(A, C), t1 = csub(A, C);                                  \
    float2 t2 = cadd(Bq, D), t3 = csub(Bq, D);                                \
    float2 t3m = make_float2(t3.y, -t3.x);  /* -i*t3 */                       \
    A  = cadd(t0, t2);                                                        \
    Bq = cmulf(cadd(t1, t3m), W1);                                            \
    C  = cmulf(csub(t0, t2), W2);                                             \
    D  = cmulf(csub(t1, t3m), W3);                                            \
} while (0)

// ---------------- radix-2 smem FFT (hilbert only, negligible cost) ----------------
template <bool INV>
__device__ __forceinline__ void fft1024(float2* sm, const float2* tw, int tid) {
#pragma unroll
    for (int e = 0; e < 4; e++) {
        int i = tid + e * NT;
        int j = __brev(i) >> 22;
        if (i < j) { float2 t = sm[i]; sm[i] = sm[j]; sm[j] = t; }
    }
    __syncthreads();
#pragma unroll
    for (int s = 1; s <= 10; s++) {
        int half = 1 << (s - 1);
#pragma unroll
        for (int e = 0; e < 2; e++) {
            int m   = tid + e * NT;
            int pos = m & (half - 1);
            int i0  = ((m >> (s - 1)) << s) + pos;
            int i1  = i0 + half;
            float2 w = tw[pos << (10 - s)];
            float wy = INV ? -w.y : w.y;
            float2 q = sm[i1];
            float2 v = make_float2(q.x * w.x - q.y * wy, q.x * wy + q.y * w.x);
            float2 u = sm[i0];
            sm[i0] = make_float2(u.x + v.x, u.y + v.y);
            sm[i1] = make_float2(u.x - v.x, u.y - v.y);
        }
        __syncthreads();
    }
    if (INV) {
        const float sc = 1.0f / (float)NN;
#pragma unroll
        for (int e = 0; e < 4; e++) { int i = tid + e * NT; sm[i].x *= sc; sm[i].y *= sc; }
        __syncthreads();
    }
}

// ---------------- kernel 1: init ----------------
__global__ void init_kernel(float* out) {
    int t = threadIdx.x;
    if (t == 0) out[0] = 0.0f;
    if (t < BB) {
        g_accS[t] = 0.0; g_accST[t] = 0.0; g_accT[t] = 0.0; g_accT2[t] = 0.0;
        g_accMax[t] = 0u;
    }
    if (t < 512) {
        double ang = -2.0 * 3.14159265358979323846 * (double)t / (double)NN;
        g_tw[t] = make_float2((float)cos(ang), (float)sin(ang));
    }
}

// ---------------- kernel 2: hilbert + modulation ----------------
__global__ void hilbert_kernel(const float* __restrict__ pred) {
    __shared__ float2 sm[NN];
    __shared__ float2 tw[NN / 2];
    int b = blockIdx.x, tid = threadIdx.x;
#pragma unroll
    for (int e = 0; e < 2; e++) tw[tid + e * NT] = g_tw[tid + e * NT];
#pragma unroll
    for (int e = 0; e < 4; e++) {
        int i = tid + e * NT;
        sm[i] = make_float2(pred[b * NN + i], 0.0f);
    }
    __syncthreads();
    fft1024<false>(sm, tw, tid);
#pragma unroll
    for (int e = 0; e < 4; e++) {
        int i = tid + e * NT;
        float h = (i < NN / 2) ? 0.0f : ((i == NN / 2) ? 1.0f : 2.0f);
        sm[i].x *= h; sm[i].y *= h;
    }
    __syncthreads();
    fft1024<true>(sm, tw, tid);
#pragma unroll
    for (int e = 0; e < 4; e++) {
        int i = tid + e * NT;
        float2 a = sm[i];
        g_pa[b * NN + i] = a;
        float ang = (float)(2.0 * 1175000000000000.0 * 1.5e-15 * (double)(i - 512));
        float cs = cosf(ang), sn = sinf(ang);
        g_pam[b * NN + i] = cmulf(a, make_float2(cs, -sn));
    }
}

// ---------------- kernel 3: SHG, radix-4 register FFT ----------------
// 4 groups of 64 threads per block; each group does 4 rows. grid (64, 32).
#define SWZ(t) ((t) ^ (((t) >> 4) & 15))

__global__ __launch_bounds__(256, 2) void shg_kernel(const float* __restrict__ tref) {
    extern __shared__ char sraw[];
    float2* paS     = (float2*)sraw;            // 1024
    float2* pamS    = paS + NN;                 // 1024
    float2* twS     = pamS + NN;                // 256
    float2* workAll = twS + 256;                // 4*1024
    float*  trsAll  = (float*)(workAll + 4 * NN);  // 4*1024 floats

    int tid = threadIdx.x;
    int b = blockIdx.y;
    int g = tid >> 6, lt = tid & 63;
    float2* work = workAll + g * NN;
    float*  trs  = trsAll + g * NN;

    for (int i = tid; i < NN; i += NT) { paS[i] = g_pa[b * NN + i]; pamS[i] = g_pam[b * NN + i]; }
    if (tid < 256) twS[tid] = g_tw[tid];
    __syncthreads();

    const float DT2 = 2.25e-30f;
    const float* base = tref + (size_t)b * NN * NN;
    int mcoef = lt >> 2, ccoef = lt & 3;
    // digit-reversal constant: p = 4*lt + 256*v + j -> k = 256*j + kbase + v
    int kbase = 64 * (lt & 3) + 16 * ((lt >> 2) & 3) + 4 * (lt >> 4);

    float  lmax = 0.0f;
    double dS = 0.0, dST = 0.0, dT = 0.0, dT2a = 0.0;

    for (int rr = 0; rr < 4; rr++) {
        int d = blockIdx.x * 16 + g * 4 + rr;
        int delay = d - 512;
        const float4* row4 = (const float4*)(base + (size_t)d * NN);

        // prefetch tref row (consumed at end of iteration)
        float4 tv4[4];
#pragma unroll
        for (int j = 0; j < 4; j++) tv4[j] = row4[lt + 64 * j];

        // build input in registers, layout A: r[e] = c[lt + 64e]
        float2 r[16];
#pragma unroll
        for (int e = 0; e < 16; e++) {
            int t  = lt + 64 * e;
            int t2 = (t - delay) & (NN - 1);
            r[e] = cmulf(pamS[t], paS[t2]);
        }
        // stage 0 (L=1024): quads (c2, c2+4, c2+8, c2+12), q = lt + 64*c2
#pragma unroll
        for (int c2 = 0; c2 < 4; c2++) {
            float2 w1 = twS[lt + 64 * c2];
            float2 w2 = cmulf(w1, w1), w3 = cmulf(w1, w2);
            BFLY4(r[c2], r[c2 + 4], r[c2 + 8], r[c2 + 12], w1, w2, w3);
        }
        // stage 1 (L=256): quads (4B..4B+3), q = lt, W_256^q = W_1024^{4q}
        {
            float2 w1 = twS[4 * lt];
            float2 w2 = cmulf(w1, w1), w3 = cmulf(w1, w2);
#pragma unroll
            for (int B = 0; B < 4; B++)
                BFLY4(r[4 * B], r[4 * B + 1], r[4 * B + 2], r[4 * B + 3], w1, w2, w3);
        }
        // exchange 1: layout A -> layout B (t = 64m + c + 4j)
#pragma unroll
        for (int e = 0; e < 16; e++) { int t = lt + 64 * e; work[SWZ(t)] = r[e]; }
        gbar(g + 1);
#pragma unroll
        for (int j = 0; j < 16; j++) { int t = 64 * mcoef + ccoef + 4 * j; r[j] = work[SWZ(t)]; }
        // stage 2 (L=64): quads (j0, j0+4, j0+8, j0+12), q = c + 4*j0, W_64^q = W_1024^{16q}
#pragma unroll
        for (int j0 = 0; j0 < 4; j0++) {
            float2 w1 = twS[16 * (ccoef + 4 * j0)];
            float2 w2 = cmulf(w1, w1), w3 = cmulf(w1, w2);
            BFLY4(r[j0], r[j0 + 4], r[j0 + 8], r[j0 + 12], w1, w2, w3);
        }
        // stage 3 (L=16): quads (4h..4h+3), q = c, W_16^c = W_1024^{64c}
        {
            float2 w1 = twS[64 * ccoef];
            float2 w2 = cmulf(w1, w1), w3 = cmulf(w1, w2);
#pragma unroll
            for (int h = 0; h < 4; h++)
                BFLY4(r[4 * h], r[4 * h + 1], r[4 * h + 2], r[4 * h + 3], w1, w2, w3);
        }
        // exchange 2: layout B -> layout C (t = 4*(lt + 64v) + u); also stage tref row
        gbar(g + 1);
#pragma unroll
        for (int j = 0; j < 16; j++) { int t = 64 * mcoef + ccoef + 4 * j; work[SWZ(t)] = r[j]; }
        float rT = 0.0f, rT2 = 0.0f;
#pragma unroll
        for (int j = 0; j < 4; j++) {
            float4 v4 = tv4[j];
            ((float4*)trs)[lt + 64 * j] = v4;
            rT  += v4.x + v4.y + v4.z + v4.w;
            rT2 += v4.x * v4.x + v4.y * v4.y + v4.z * v4.z + v4.w * v4.w;
        }
        gbar(g + 1);
#pragma unroll
        for (int v = 0; v < 4; v++)
#pragma unroll
            for (int u = 0; u < 4; u++) {
                int t = 4 * lt + 256 * v + u;
                r[4 * v + u] = work[SWZ(t)];
            }
        // stage 4 (L=4, no twiddles) + Sv reduction; freq k = 256*u + kbase + v
        float rS = 0.0f, rST = 0.0f;
#pragma unroll
        for (int v = 0; v < 4; v++) {
            float2 a = r[4 * v], bq = r[4 * v + 1], cq = r[4 * v + 2], dq = r[4 * v + 3];
            float2 t0 = cadd(a, cq), t1 = csub(a, cq);
            float2 t2 = cadd(bq, dq), t3 = csub(bq, dq);
            float2 t3m = make_float2(t3.y, -t3.x);
            float2 y0 = cadd(t0, t2);
            float2 y1 = cadd(t1, t3m);
            float2 y2 = csub(t0, t2);
            float2 y3 = csub(t1, t3m);
            int kb = kbase + v;
            float s0 = (y0.x * y0.x + y0.y * y0.y) * DT2;
            float s1 = (y1.x * y1.x + y1.y * y1.y) * DT2;
            float s2 = (y2.x * y2.x + y2.y * y2.y) * DT2;
            float s3 = (y3.x * y3.x + y3.y * y3.y) * DT2;
            lmax = fmaxf(lmax, fmaxf(fmaxf(s0, s1), fmaxf(s2, s3)));
            rS += s0 + s1 + s2 + s3;
            rST += s0 * trs[kb ^ 512];
            rST += s1 * trs[(kb + 256) ^ 512];
            rST += s2 * trs[(kb + 512) ^ 512];
            rST += s3 * trs[(kb + 768) ^ 512];
        }
        dS += rS; dST += rST; dT += rT; dT2a += rT2;
        gbar(g + 1);
    }

    // block reduction
    double vS = dS, vST = dST, vT = dT, vT2 = dT2a; float vM = lmax;
#pragma unroll
    for (int o = 16; o > 0; o >>= 1) {
        vS  += __shfl_down_sync(0xffffffffu, vS,  o);
        vST += __shfl_down_sync(0xffffffffu, vST, o);
        vT  += __shfl_down_sync(0xffffffffu, vT,  o);
        vT2 += __shfl_down_sync(0xffffffffu, vT2, o);
        vM   = fmaxf(vM, __shfl_down_sync(0xffffffffu, vM, o));
    }
    __shared__ double sS[8], sST[8], sT[8], sT2[8];
    __shared__ float  sM[8];
    int w = tid >> 5, lane = tid & 31;
    if (lane == 0) { sS[w] = vS; sST[w] = vST; sT[w] = vT; sT2[w] = vT2; sM[w] = vM; }
    __syncthreads();
    if (tid == 0) {
        double aS = 0, aST = 0, aT = 0, aT2 = 0; float aM = 0.0f;
#pragma unroll
        for (int i = 0; i < 8; i++) {
            aS += sS[i]; aST += sST[i]; aT += sT[i]; aT2 += sT2[i];
            aM = fmaxf(aM, sM[i]);
        }
        atomicAdd(&g_accS[b],  aS);
        atomicAdd(&g_accST[b], aST);
        atomicAdd(&g_accT[b],  aT);
        atomicAdd(&g_accT2[b], aT2);
        atomicMax(&g_accMax[b], __float_as_uint(aM));
    }
}

// ---------------- kernel 4: MSE + frog + final mean ----------------
__global__ void loss_kernel(const float* __restrict__ label, float* out) {
    int b = blockIdx.x, tid = threadIdx.x;
    const float* lr = label + (size_t)b * 2 * NN;
    const float* li = lr + NN;

    __shared__ int s_frR, s_laR, s_frI, s_laI;
    if (tid == 0) { s_frR = NN; s_laR = -1; s_frI = NN; s_laI = -1; }
    __syncthreads();
    int frR = NN, laR = -1, frI = NN, laI = -1;
    for (int t = tid; t < NN; t += NT) {
        if (fabsf(lr[t]) > 0.01f) { frR = min(frR, t); laR = max(laR, t); }
        if (fabsf(li[t]) > 0.01f) { frI = min(frI, t); laI = max(laI, t); }
    }
    atomicMin(&s_frR, frR); atomicMax(&s_laR, laR);
    atomicMin(&s_frI, frI); atomicMax(&s_laI, laI);
    __syncthreads();
    int fr_r = (s_frR == NN) ? 0 : s_frR;
    int la_r = (s_laR < 0) ? (NN - 1) : s_laR;
    int fr_i = (s_frI == NN) ? 0 : s_frI;
    int la_i = (s_laI < 0) ? (NN - 1) : s_laI;
    int first = min(fr_r, fr_i);
    int last  = max(la_r, la_i);

    float sR = 0, sI = 0, sInt = 0, sPh = 0;
    for (int t = tid; t < NN; t += NT) {
        float2 p = g_pa[b * NN + t];
        float LR = lr[t], LI = li[t];
        bool inr = (t >= first) && (t < last);
        float pm = inr ? 10.0f : 1.0f;
        float dr = p.x - LR, di = p.y - LI;
        float pint = p.x * p.x + p.y * p.y;
        float lint = LR * LR + LI * LI;
        float dint = pint - lint;
        sR   += dr * dr * pm;
        sI   += di * di * pm;
        sInt += dint * dint * pm;
        if (inr) {
            float dp = atan2f(p.y, p.x) - atan2f(LI, LR);
            sPh += dp * dp;
        }
    }
#pragma unroll
    for (int o = 16; o > 0; o >>= 1) {
        sR   += __shfl_down_sync(0xffffffffu, sR, o);
        sI   += __shfl_down_sync(0xffffffffu, sI, o);
        sInt += __shfl_down_sync(0xffffffffu, sInt, o);
        sPh  += __shfl_down_sync(0xffffffffu, sPh, o);
    }
    __shared__ float rA[8], rBv[8], rC[8], rD[8];
    int w = tid >> 5, lane = tid & 31;
    if (lane == 0) { rA[w] = sR; rBv[w] = sI; rC[w] = sInt; rD[w] = sPh; }
    __syncthreads();
    if (tid == 0) {
        float aR = 0, aI = 0, aInt = 0, aPh = 0;
#pragma unroll
        for (int i = 0; i < 8; i++) { aR += rA[i]; aI += rBv[i]; aInt += rC[i]; aPh += rD[i]; }
        float mse = (aR + aI + aInt + aPh) * (1.0f / NN) * 0.25f;

        double M    = (double)__uint_as_float(g_accMax[b]);
        double sum1 = g_accST[b] / M;
        double mu   = sum1 / g_accT2[b];
        double diff = g_accS[b] / M - mu * g_accT[b];
        double r2   = diff * diff;
        float frog = (r2 == 0.0) ? 0.0f : (float)(sqrt(r2) / (double)NN);

        atomicAdd(out, (mse + frog) * (1.0f / BB));
    }
}

// ---------------- launch ----------------
extern "C" void kernel_launch(void* const* d_in, const int* in_sizes, int n_in,
                              void* d_out, int out_size) {
    const float* pred  = (const float*)d_in[0];
    const float* label = (const float*)d_in[1];
    const float* shg   = (const float*)d_in[2];
    float* out = (float*)d_out;

    const int SHG_SMEM = (NN * 2 + 256 + 4 * NN) * sizeof(float2) + 4 * NN * sizeof(float);
    static int attr_done = 0;
    if (!attr_done) {
        cudaFuncSetAttribute(shg_kernel, cudaFuncAttributeMaxDynamicSharedMemorySize, SHG_SMEM);
        attr_done = 1;
    }

    init_kernel<<<1, 512>>>(out);
    hilbert_kernel<<<BB, NT>>>(pred);
    shg_kernel<<<dim3(64, BB), NT, SHG_SMEM>>>(shg);
    loss_kernel<<<BB, NT>>>(label, out);
}